// round 16
// baseline (speedup 1.0000x reference)
#include <cuda_runtime.h>
#include <cuda_fp16.h>
#include <mma.h>
#include <math.h>
#include <stdint.h>

using namespace nvcuda;

// Problem constants
#define T_TOK 8192
#define HID   2048
#define NEXP  64
#define IDIM  768
#define TOPK  8
#define TK    (T_TOK*TOPK)               // 65536 pairs
#define TILE_M 128
#define MAX_TILES ((TK/TILE_M) + NEXP)   // 576
#define MAXPAD (MAX_TILES*TILE_M)        // 73728
#define WELEM  ((size_t)NEXP*IDIM*HID)   // 100663296 per weight tensor
#define RTOK   32                         // tokens per router block

// GEMM geometry (R12-identical)
#define BK       64
#define HS_STRIDE 72
#define A_HL     (128*HS_STRIDE)
#define B_HL     (256*HS_STRIDE)
#define ST_HL    (A_HL + B_HL)
#define STAGES   4
#define GEMM_SMEM (STAGES*ST_HL*2)        // 221184 B
#define GU_STRIDE 132
#define CS_STRIDE 260

// ---------------- scratch ----------------
__device__ int    g_topk_e[TK];
__device__ float  g_topk_w[TK];
__device__ int    g_counts[NEXP];
__device__ int    g_cursor[NEXP];
__device__ int    g_tile_expert[MAX_TILES];
__device__ int    g_token_list[MAXPAD];
__device__ int    g_pair_slot[TK];
__device__ __half g_acth[(size_t)MAXPAD * IDIM];
__device__ __half g_pairouth[(size_t)MAXPAD * HID];
__device__ __half g_xh[(size_t)T_TOK * HID];
__device__ __half g_gph[WELEM];
__device__ __half g_uph[WELEM];
__device__ __half g_dph[WELEM];

// ---------------- cp.async helpers ----------------
__device__ __forceinline__ void cp_async16(uint32_t dst, const void* src, int sz) {
    asm volatile("cp.async.cg.shared.global [%0], [%1], 16, %2;\n" :: "r"(dst), "l"(src), "r"(sz));
}
__device__ __forceinline__ void cp_commit() { asm volatile("cp.async.commit_group;\n"); }
__device__ __forceinline__ void cp_wait2()  { asm volatile("cp.async.wait_group 2;\n"); }

// ---------------- fp32 -> fp16 conversion (8 elems/thread) ----------------
__global__ __launch_bounds__(256) void k_cvt(const float4* __restrict__ s,
                                             uint4* __restrict__ d, size_t n8) {
    size_t i = (size_t)blockIdx.x * 256 + threadIdx.x;
    if (i < n8) {
        float4 a = s[2 * i], b = s[2 * i + 1];
        __half2 h0 = __floats2half2_rn(a.x, a.y);
        __half2 h1 = __floats2half2_rn(a.z, a.w);
        __half2 h2 = __floats2half2_rn(b.x, b.y);
        __half2 h3 = __floats2half2_rn(b.z, b.w);
        uint4 o;
        o.x = *(unsigned*)&h0; o.y = *(unsigned*)&h1;
        o.z = *(unsigned*)&h2; o.w = *(unsigned*)&h3;
        d[i] = o;
    }
}

// ---------------- reset ----------------
__global__ void k_reset() {
    int idx = blockIdx.x * blockDim.x + threadIdx.x;
    if (idx < MAXPAD)    g_token_list[idx] = -1;
    if (idx < MAX_TILES) g_tile_expert[idx] = -1;
    if (idx < NEXP)      g_counts[idx] = 0;
}

// ---------------- router: 32 tokens/block (R12-identical) ------------------
__global__ __launch_bounds__(256) void k_router(
    const float* __restrict__ x, const float* __restrict__ gw,
    float* __restrict__ out_logits, int write_logits)
{
    __shared__ float xs[RTOK * 64];
    __shared__ float ws[64 * 65];
    __shared__ float lg[RTOK * 65];

    int tid = threadIdx.x;
    int tok0 = blockIdx.x * RTOK;
    int e  = tid & 63;
    int tr = tid >> 6;
    float acc[8];
    #pragma unroll
    for (int i = 0; i < 8; i++) acc[i] = 0.f;

    for (int kc = 0; kc < HID; kc += 64) {
        {
            int r  = tid >> 4;
            int c4 = tid & 15;
            float4 v0 = *(const float4*)(x + (size_t)(tok0 + r) * HID + kc + c4 * 4);
            *(float4*)&xs[r * 64 + c4 * 4] = v0;
            float4 v1 = *(const float4*)(x + (size_t)(tok0 + r + 16) * HID + kc + c4 * 4);
            *(float4*)&xs[(r + 16) * 64 + c4 * 4] = v1;
        }
        #pragma unroll
        for (int p = 0; p < 16; p++) {
            int lin = p * 256 + tid;
            int r = lin >> 6, c = lin & 63;
            ws[r * 65 + c] = gw[(size_t)r * HID + kc + c];
        }
        __syncthreads();
        #pragma unroll 4
        for (int kk = 0; kk < 64; kk++) {
            float wv = ws[e * 65 + kk];
            #pragma unroll
            for (int t = 0; t < 8; t++)
                acc[t] += xs[(tr * 8 + t) * 64 + kk] * wv;
        }
        __syncthreads();
    }
    #pragma unroll
    for (int t = 0; t < 8; t++)
        lg[(tr * 8 + t) * 65 + e] = acc[t];
    __syncthreads();

    if (write_logits) {
        #pragma unroll
        for (int p = 0; p < 8; p++) {
            int lin = p * 256 + tid;
            int t = lin >> 6, ee = lin & 63;
            out_logits[(size_t)(tok0 + t) * NEXP + ee] = lg[t * 65 + ee];
        }
    }

    if (tid < RTOK) {
        int t = tid;
        float* l = &lg[t * 65];
        float m = -1e30f;
        for (int i = 0; i < NEXP; i++) m = fmaxf(m, l[i]);
        for (int i = 0; i < NEXP; i++) l[i] = expf(l[i] - m);
        int   sel[TOPK];
        float sp[TOPK];
        float wsum = 0.f;
        #pragma unroll
        for (int k = 0; k < TOPK; k++) {
            float bp = -1.f; int be = -1;
            for (int i = 0; i < NEXP; i++)
                if (l[i] > bp) { bp = l[i]; be = i; }
            sel[k] = be; sp[k] = bp; wsum += bp;
            l[be] = -1.f;
        }
        float inv = 1.f / wsum;
        #pragma unroll
        for (int k = 0; k < TOPK; k++) {
            int idx = (tok0 + t) * TOPK + k;
            g_topk_e[idx] = sel[k];
            g_topk_w[idx] = sp[k] * inv;
            atomicAdd(&g_counts[sel[k]], 1);
        }
    }
}

// ---------------- scan: warp-parallel prefix ----------------
__global__ void k_scan() {
    int lane = threadIdx.x;
    int e0 = lane * 2, e1 = lane * 2 + 1;
    int c0 = g_counts[e0], c1 = g_counts[e1];
    int n0 = (c0 + TILE_M - 1) / TILE_M;
    int n1 = (c1 + TILE_M - 1) / TILE_M;
    int pair = n0 + n1;
    int xval = pair;
    #pragma unroll
    for (int d = 1; d < 32; d <<= 1) {
        int y = __shfl_up_sync(0xffffffffu, xval, d);
        if (lane >= d) xval += y;
    }
    int t0 = xval - pair;
    int t1 = t0 + n0;
    g_cursor[e0] = t0 * TILE_M;
    g_cursor[e1] = t1 * TILE_M;
    for (int i = 0; i < n0; i++) g_tile_expert[t0 + i] = e0;
    for (int i = 0; i < n1; i++) g_tile_expert[t1 + i] = e1;
}

// ---------------- fill ----------------
__global__ void k_fill() {
    int idx = blockIdx.x * blockDim.x + threadIdx.x;
    if (idx < TK) {
        int e = g_topk_e[idx];
        int p = atomicAdd(&g_cursor[e], 1);
        g_token_list[p] = idx >> 3;
        g_pair_slot[idx] = p;
    }
}

typedef wmma::fragment<wmma::matrix_a, 16, 16, 16, __half, wmma::row_major> FragA;
typedef wmma::fragment<wmma::matrix_b, 16, 16, 16, __half, wmma::col_major> FragB;
typedef wmma::fragment<wmma::accumulator, 16, 16, 16, float> FragC;

// ---------------- fused gate+up GEMM (R12-identical) -----------------------
__global__ __launch_bounds__(256, 1) void k_gemm_gu(
    const __half* __restrict__ Xh,
    const __half* __restrict__ Gp, const __half* __restrict__ Up)
{
    extern __shared__ __half smh[];
    __shared__ int toks[TILE_M];

    int tileM = blockIdx.x;
    int eid = g_tile_expert[tileM];
    if (eid < 0) return;
    int slot0 = tileM * TILE_M;
    int n0 = blockIdx.y * 128;
    const __half* Gexp = Gp + (size_t)eid * IDIM * HID;
    const __half* Uexp = Up + (size_t)eid * IDIM * HID;

    int tid = threadIdx.x;
    if (tid < TILE_M) toks[tid] = g_token_list[slot0 + tid];
    __syncthreads();

    uint32_t s_base = (uint32_t)__cvta_generic_to_shared(smh);

    auto issue = [&](int s, int k0) {
        uint32_t ab = s_base + (uint32_t)(s * ST_HL) * 2;
        uint32_t bb = ab + (uint32_t)A_HL * 2;
        #pragma unroll
        for (int p = 0; p < 4; p++) {
            int lin = p * 256 + tid;
            int r = lin >> 3, c = lin & 7;
            uint32_t doff = (uint32_t)(r * HS_STRIDE + c * 8) * 2;
            int tk = toks[r];
            const __half* src = Xh + (size_t)(tk < 0 ? 0 : tk) * HID + k0 + c * 8;
            cp_async16(ab + doff, src, (tk < 0) ? 0 : 16);
        }
        #pragma unroll
        for (int p = 0; p < 8; p++) {
            int lin = p * 256 + tid;
            int r = lin >> 3, c = lin & 7;
            uint32_t doff = (uint32_t)(r * HS_STRIDE + c * 8) * 2;
            const __half* src = (r < 128)
                ? Gexp + (size_t)(n0 + r) * HID + k0 + c * 8
                : Uexp + (size_t)(n0 + r - 128) * HID + k0 + c * 8;
            cp_async16(bb + doff, src, 16);
        }
        cp_commit();
    };

    FragC cg[4][2], cu[4][2];
    #pragma unroll
    for (int i = 0; i < 4; i++)
        #pragma unroll
        for (int j = 0; j < 2; j++) {
            wmma::fill_fragment(cg[i][j], 0.f);
            wmma::fill_fragment(cu[i][j], 0.f);
        }

    int wid = tid >> 5;
    int wm = wid & 1;
    int wn = wid >> 1;

    const int KT = HID / BK;   // 32
    issue(0, 0);
    issue(1, BK);
    issue(2, 2 * BK);

    for (int kt = 0; kt < KT; kt++) {
        cp_wait2();
        __syncthreads();
        if (kt + 3 < KT) issue((kt + 3) % STAGES, (kt + 3) * BK);

        __half* As = smh + (kt % STAGES) * ST_HL;
        __half* Bs = As + A_HL;

        #pragma unroll
        for (int kk = 0; kk < BK; kk += 16) {
            FragA a[4];
            FragB bg[2], bu[2];
            #pragma unroll
            for (int i = 0; i < 4; i++)
                wmma::load_matrix_sync(a[i], As + (wm * 64 + i * 16) * HS_STRIDE + kk, HS_STRIDE);
            #pragma unroll
            for (int j = 0; j < 2; j++) {
                wmma::load_matrix_sync(bg[j], Bs + (wn * 32 + j * 16) * HS_STRIDE + kk, HS_STRIDE);
                wmma::load_matrix_sync(bu[j], Bs + (128 + wn * 32 + j * 16) * HS_STRIDE + kk, HS_STRIDE);
            }
            #pragma unroll
            for (int i = 0; i < 4; i++)
                #pragma unroll
                for (int j = 0; j < 2; j++) {
                    wmma::mma_sync(cg[i][j], a[i], bg[j], cg[i][j]);
                    wmma::mma_sync(cu[i][j], a[i], bu[j], cu[i][j]);
                }
        }
        __syncthreads();
    }

    float* Gs = (float*)smh;
    float* Us = Gs + 128 * GU_STRIDE;
    #pragma unroll
    for (int i = 0; i < 4; i++)
        #pragma unroll
        for (int j = 0; j < 2; j++) {
            wmma::store_matrix_sync(Gs + (wm * 64 + i * 16) * GU_STRIDE + wn * 32 + j * 16,
                                    cg[i][j], GU_STRIDE, wmma::mem_row_major);
            wmma::store_matrix_sync(Us + (wm * 64 + i * 16) * GU_STRIDE + wn * 32 + j * 16,
                                    cu[i][j], GU_STRIDE, wmma::mem_row_major);
        }
    __syncthreads();
    #pragma unroll
    for (int p = 0; p < 16; p++) {
        int lin = p * 256 + tid;
        int m = lin >> 5, n4 = lin & 31;
        float4 g = *(float4*)(Gs + m * GU_STRIDE + n4 * 4);
        float4 u = *(float4*)(Us + m * GU_STRIDE + n4 * 4);
        float ax = (g.x / (1.f + expf(-g.x))) * u.x;
        float ay = (g.y / (1.f + expf(-g.y))) * u.y;
        float az = (g.z / (1.f + expf(-g.z))) * u.z;
        float aw = (g.w / (1.f + expf(-g.w))) * u.w;
        __half2 h0 = __floats2half2_rn(ax, ay);
        __half2 h1 = __floats2half2_rn(az, aw);
        uint2 o; o.x = *(unsigned*)&h0; o.y = *(unsigned*)&h1;
        *(uint2*)(g_acth + (size_t)(slot0 + m) * IDIM + n0 + n4 * 4) = o;
    }
}

// ---------------- down GEMM (R12-identical) --------------------------------
__global__ __launch_bounds__(256, 1) void k_gemm_down(const __half* __restrict__ Dp)
{
    extern __shared__ __half smh[];

    int tileM = blockIdx.x;
    int eid = g_tile_expert[tileM];
    if (eid < 0) return;
    int slot0 = tileM * TILE_M;
    int n0 = blockIdx.y * 256;
    const __half* Bexp = Dp + (size_t)eid * HID * IDIM;

    int tid = threadIdx.x;
    uint32_t s_base = (uint32_t)__cvta_generic_to_shared(smh);

    auto issue = [&](int s, int k0) {
        uint32_t ab = s_base + (uint32_t)(s * ST_HL) * 2;
        uint32_t bb = ab + (uint32_t)A_HL * 2;
        #pragma unroll
        for (int p = 0; p < 4; p++) {
            int lin = p * 256 + tid;
            int r = lin >> 3, c = lin & 7;
            uint32_t doff = (uint32_t)(r * HS_STRIDE + c * 8) * 2;
            cp_async16(ab + doff, g_acth + (size_t)(slot0 + r) * IDIM + k0 + c * 8, 16);
        }
        #pragma unroll
        for (int p = 0; p < 8; p++) {
            int lin = p * 256 + tid;
            int r = lin >> 3, c = lin & 7;
            uint32_t doff = (uint32_t)(r * HS_STRIDE + c * 8) * 2;
            cp_async16(bb + doff, Bexp + (size_t)(n0 + r) * IDIM + k0 + c * 8, 16);
        }
        cp_commit();
    };

    FragC c[4][4];
    #pragma unroll
    for (int i = 0; i < 4; i++)
        #pragma unroll
        for (int j = 0; j < 4; j++)
            wmma::fill_fragment(c[i][j], 0.f);

    int wid = tid >> 5;
    int wm = wid & 1;
    int wn = wid >> 1;

    const int KT = IDIM / BK;   // 12
    issue(0, 0);
    issue(1, BK);
    issue(2, 2 * BK);

    for (int kt = 0; kt < KT; kt++) {
        cp_wait2();
        __syncthreads();
        if (kt + 3 < KT) issue((kt + 3) % STAGES, (kt + 3) * BK);

        __half* As = smh + (kt % STAGES) * ST_HL;
        __half* Bs = As + A_HL;

        #pragma unroll
        for (int kk = 0; kk < BK; kk += 16) {
            FragA a[4];
            FragB b[4];
            #pragma unroll
            for (int i = 0; i < 4; i++)
                wmma::load_matrix_sync(a[i], As + (wm * 64 + i * 16) * HS_STRIDE + kk, HS_STRIDE);
            #pragma unroll
            for (int j = 0; j < 4; j++)
                wmma::load_matrix_sync(b[j], Bs + (wn * 64 + j * 16) * HS_STRIDE + kk, HS_STRIDE);
            #pragma unroll
            for (int i = 0; i < 4; i++)
                #pragma unroll
                for (int j = 0; j < 4; j++)
                    wmma::mma_sync(c[i][j], a[i], b[j], c[i][j]);
        }
        __syncthreads();
    }

    float* Cs = (float*)smh;
    #pragma unroll
    for (int i = 0; i < 4; i++)
        #pragma unroll
        for (int j = 0; j < 4; j++)
            wmma::store_matrix_sync(Cs + (wm * 64 + i * 16) * CS_STRIDE + wn * 64 + j * 16,
                                    c[i][j], CS_STRIDE, wmma::mem_row_major);
    __syncthreads();
    #pragma unroll
    for (int p = 0; p < 16; p++) {
        int lin = p * 256 + tid;
        int m = lin >> 5, n8 = lin & 31;
        float4 v0 = *(float4*)(Cs + m * CS_STRIDE + n8 * 8);
        float4 v1 = *(float4*)(Cs + m * CS_STRIDE + n8 * 8 + 4);
        __half2 h0 = __floats2half2_rn(v0.x, v0.y);
        __half2 h1 = __floats2half2_rn(v0.z, v0.w);
        __half2 h2 = __floats2half2_rn(v1.x, v1.y);
        __half2 h3 = __floats2half2_rn(v1.z, v1.w);
        uint4 o;
        o.x = *(unsigned*)&h0; o.y = *(unsigned*)&h1;
        o.z = *(unsigned*)&h2; o.w = *(unsigned*)&h3;
        *(uint4*)(g_pairouth + (size_t)(slot0 + m) * HID + n0 + n8 * 8) = o;
    }
}

// ---------------- combine ----------------
__global__ __launch_bounds__(256) void k_combine(float* __restrict__ out) {
    size_t idx = (size_t)blockIdx.x * 256 + threadIdx.x;
    int t  = (int)(idx >> 8);
    int h8 = (int)(idx & 255);
    float s[8] = {0.f};
    #pragma unroll
    for (int k = 0; k < TOPK; k++) {
        int pi = t * TOPK + k;
        int p = g_pair_slot[pi];
        float w = g_topk_w[pi];
        uint4 v = *(const uint4*)(g_pairouth + (size_t)p * HID + h8 * 8);
        __half2 h0 = *(__half2*)&v.x, h1 = *(__half2*)&v.y;
        __half2 h2 = *(__half2*)&v.z, h3 = *(__half2*)&v.w;
        float2 f0 = __half22float2(h0), f1 = __half22float2(h1);
        float2 f2 = __half22float2(h2), f3 = __half22float2(h3);
        s[0] += w * f0.x; s[1] += w * f0.y; s[2] += w * f1.x; s[3] += w * f1.y;
        s[4] += w * f2.x; s[5] += w * f2.y; s[6] += w * f3.x; s[7] += w * f3.y;
    }
    float4 o0 = make_float4(s[0], s[1], s[2], s[3]);
    float4 o1 = make_float4(s[4], s[5], s[6], s[7]);
    *(float4*)(out + idx * 8)     = o0;
    *(float4*)(out + idx * 8 + 4) = o1;
}

// ---------------- launch: R15 + deferred dp-cvt join -----------------------
extern "C" void kernel_launch(void* const* d_in, const int* in_sizes, int n_in,
                              void* d_out, int out_size) {
    const float* x  = (const float*)d_in[0];
    const float* gw = (const float*)d_in[1];
    const float* gp = (const float*)d_in[2];
    const float* up = (const float*)d_in[3];
    const float* dp = (const float*)d_in[4];
    float* out = (float*)d_out;
    float* out_logits = out + (size_t)T_TOK * HID;
    int write_logits = (out_size >= T_TOK * HID + T_TOK * NEXP) ? 1 : 0;

    static cudaStream_t s_w = nullptr;
    static cudaEvent_t ev_fork = nullptr, ev_b = nullptr, ev_c = nullptr;
    if (!s_w) {
        cudaStreamCreateWithFlags(&s_w, cudaStreamNonBlocking);
        cudaEventCreateWithFlags(&ev_fork, cudaEventDisableTiming);
        cudaEventCreateWithFlags(&ev_b, cudaEventDisableTiming);
        cudaEventCreateWithFlags(&ev_c, cudaEventDisableTiming);
        cudaFuncSetAttribute(k_gemm_gu,
                             cudaFuncAttributeMaxDynamicSharedMemorySize, GEMM_SMEM);
        cudaFuncSetAttribute(k_gemm_down,
                             cudaFuncAttributeMaxDynamicSharedMemorySize, GEMM_SMEM);
    }

    __half *xh_p, *gph_p, *uph_p, *dph_p;
    cudaGetSymbolAddress((void**)&xh_p,  g_xh);
    cudaGetSymbolAddress((void**)&gph_p, g_gph);
    cudaGetSymbolAddress((void**)&uph_p, g_uph);
    cudaGetSymbolAddress((void**)&dph_p, g_dph);

    const size_t W8 = WELEM / 8;
    const size_t X8 = (size_t)T_TOK * HID / 8;

    // fork: weight conversions on the side stream (gp+up gate gu; dp gates down)
    cudaEventRecord(ev_fork, 0);
    cudaStreamWaitEvent(s_w, ev_fork, 0);
    k_cvt<<<(unsigned)((W8 + 255) / 256), 256, 0, s_w>>>((const float4*)gp, (uint4*)gph_p, W8);
    k_cvt<<<(unsigned)((W8 + 255) / 256), 256, 0, s_w>>>((const float4*)up, (uint4*)uph_p, W8);
    cudaEventRecord(ev_b, s_w);
    k_cvt<<<(unsigned)((W8 + 255) / 256), 256, 0, s_w>>>((const float4*)dp, (uint4*)dph_p, W8);
    cudaEventRecord(ev_c, s_w);

    // main stream: router chain + x conversion (overlapped with weight cvt)
    k_reset<<<(MAXPAD + 255) / 256, 256>>>();
    k_router<<<T_TOK / RTOK, 256>>>(x, gw, out_logits, write_logits);
    k_scan<<<1, 32>>>();
    k_fill<<<(TK + 255) / 256, 256>>>();
    k_cvt<<<(unsigned)((X8 + 255) / 256), 256>>>((const float4*)x, (uint4*)xh_p, X8);

    // gu needs only gp+up; dp cvt overlaps the gu GEMM
    cudaStreamWaitEvent(0, ev_b, 0);
    k_gemm_gu<<<dim3(MAX_TILES, IDIM / 128), 256, GEMM_SMEM>>>(xh_p, gph_p, uph_p);

    cudaStreamWaitEvent(0, ev_c, 0);
    k_gemm_down<<<dim3(MAX_TILES, HID / 256), 256, GEMM_SMEM>>>(dph_p);

    k_combine<<<T_TOK * HID / 8 / 256, 256>>>(out);
}

// round 17
// speedup vs baseline: 1.1223x; 1.1223x over previous
#include <cuda_runtime.h>
#include <cuda_fp16.h>
#include <mma.h>
#include <math.h>
#include <stdint.h>

using namespace nvcuda;

// Problem constants
#define T_TOK 8192
#define HID   2048
#define NEXP  64
#define IDIM  768
#define TOPK  8
#define TK    (T_TOK*TOPK)               // 65536 pairs
#define TILE_M 128
#define MAX_TILES ((TK/TILE_M) + NEXP)   // 576
#define MAXPAD (MAX_TILES*TILE_M)        // 73728
#define WELEM  ((size_t)NEXP*IDIM*HID)   // 100663296 per weight tensor
#define RTOK   32

// GEMM geometry: 128-thread CTAs, 3-stage pipeline, 2 CTAs/SM
#define BK       64
#define HS_STRIDE 72
#define A_HL     (128*HS_STRIDE)          // 9216 halfs (A tile: 128 x 64h)
#define B_HL     (128*HS_STRIDE)          // 9216 halfs (B tile: 128 rows x 64h)
#define ST_HL    (A_HL + B_HL)            // 18432 halfs = 36864 B / stage
#define STAGES   3
#define GEMM_SMEM (STAGES*ST_HL*2)        // 110592 B  -> 2 CTAs/SM
#define ACT_STRIDE 68                     // gu epilogue fp32 stride (34816 B)
#define CS_STRIDE 132                     // down epilogue fp32 stride (67584 B)

// ---------------- scratch ----------------
__device__ int    g_topk_e[TK];
__device__ float  g_topk_w[TK];
__device__ int    g_counts[NEXP];
__device__ int    g_cursor[NEXP];
__device__ int    g_tile_expert[MAX_TILES];
__device__ int    g_token_list[MAXPAD];
__device__ int    g_pair_slot[TK];
__device__ __half g_acth[(size_t)MAXPAD * IDIM];
__device__ __half g_pairouth[(size_t)MAXPAD * HID];
__device__ __half g_xh[(size_t)T_TOK * HID];
__device__ __half g_gph[WELEM];
__device__ __half g_uph[WELEM];
__device__ __half g_dph[WELEM];

// ---------------- cp.async helpers ----------------
__device__ __forceinline__ void cp_async16(uint32_t dst, const void* src, int sz) {
    asm volatile("cp.async.cg.shared.global [%0], [%1], 16, %2;\n" :: "r"(dst), "l"(src), "r"(sz));
}
__device__ __forceinline__ void cp_commit() { asm volatile("cp.async.commit_group;\n"); }
__device__ __forceinline__ void cp_wait1()  { asm volatile("cp.async.wait_group 1;\n"); }

// ---------------- fp32 -> fp16 conversion ----------------
__global__ __launch_bounds__(256) void k_cvt(const float4* __restrict__ s,
                                             uint4* __restrict__ d, size_t n8) {
    size_t i = (size_t)blockIdx.x * 256 + threadIdx.x;
    if (i < n8) {
        float4 a = s[2 * i], b = s[2 * i + 1];
        __half2 h0 = __floats2half2_rn(a.x, a.y);
        __half2 h1 = __floats2half2_rn(a.z, a.w);
        __half2 h2 = __floats2half2_rn(b.x, b.y);
        __half2 h3 = __floats2half2_rn(b.z, b.w);
        uint4 o;
        o.x = *(unsigned*)&h0; o.y = *(unsigned*)&h1;
        o.z = *(unsigned*)&h2; o.w = *(unsigned*)&h3;
        d[i] = o;
    }
}

// ---------------- reset ----------------
__global__ void k_reset() {
    int idx = blockIdx.x * blockDim.x + threadIdx.x;
    if (idx < MAXPAD)    g_token_list[idx] = -1;
    if (idx < MAX_TILES) g_tile_expert[idx] = -1;
    if (idx < NEXP)      g_counts[idx] = 0;
}

// ---------------- router: 32 tokens/block (R12-identical) ------------------
__global__ __launch_bounds__(256) void k_router(
    const float* __restrict__ x, const float* __restrict__ gw,
    float* __restrict__ out_logits, int write_logits)
{
    __shared__ float xs[RTOK * 64];
    __shared__ float ws[64 * 65];
    __shared__ float lg[RTOK * 65];

    int tid = threadIdx.x;
    int tok0 = blockIdx.x * RTOK;
    int e  = tid & 63;
    int tr = tid >> 6;
    float acc[8];
    #pragma unroll
    for (int i = 0; i < 8; i++) acc[i] = 0.f;

    for (int kc = 0; kc < HID; kc += 64) {
        {
            int r  = tid >> 4;
            int c4 = tid & 15;
            float4 v0 = *(const float4*)(x + (size_t)(tok0 + r) * HID + kc + c4 * 4);
            *(float4*)&xs[r * 64 + c4 * 4] = v0;
            float4 v1 = *(const float4*)(x + (size_t)(tok0 + r + 16) * HID + kc + c4 * 4);
            *(float4*)&xs[(r + 16) * 64 + c4 * 4] = v1;
        }
        #pragma unroll
        for (int p = 0; p < 16; p++) {
            int lin = p * 256 + tid;
            int r = lin >> 6, c = lin & 63;
            ws[r * 65 + c] = gw[(size_t)r * HID + kc + c];
        }
        __syncthreads();
        #pragma unroll 4
        for (int kk = 0; kk < 64; kk++) {
            float wv = ws[e * 65 + kk];
            #pragma unroll
            for (int t = 0; t < 8; t++)
                acc[t] += xs[(tr * 8 + t) * 64 + kk] * wv;
        }
        __syncthreads();
    }
    #pragma unroll
    for (int t = 0; t < 8; t++)
        lg[(tr * 8 + t) * 65 + e] = acc[t];
    __syncthreads();

    if (write_logits) {
        #pragma unroll
        for (int p = 0; p < 8; p++) {
            int lin = p * 256 + tid;
            int t = lin >> 6, ee = lin & 63;
            out_logits[(size_t)(tok0 + t) * NEXP + ee] = lg[t * 65 + ee];
        }
    }

    if (tid < RTOK) {
        int t = tid;
        float* l = &lg[t * 65];
        float m = -1e30f;
        for (int i = 0; i < NEXP; i++) m = fmaxf(m, l[i]);
        for (int i = 0; i < NEXP; i++) l[i] = expf(l[i] - m);
        int   sel[TOPK];
        float sp[TOPK];
        float wsum = 0.f;
        #pragma unroll
        for (int k = 0; k < TOPK; k++) {
            float bp = -1.f; int be = -1;
            for (int i = 0; i < NEXP; i++)
                if (l[i] > bp) { bp = l[i]; be = i; }
            sel[k] = be; sp[k] = bp; wsum += bp;
            l[be] = -1.f;
        }
        float inv = 1.f / wsum;
        #pragma unroll
        for (int k = 0; k < TOPK; k++) {
            int idx = (tok0 + t) * TOPK + k;
            g_topk_e[idx] = sel[k];
            g_topk_w[idx] = sp[k] * inv;
            atomicAdd(&g_counts[sel[k]], 1);
        }
    }
}

// ---------------- scan ----------------
__global__ void k_scan() {
    int lane = threadIdx.x;
    int e0 = lane * 2, e1 = lane * 2 + 1;
    int c0 = g_counts[e0], c1 = g_counts[e1];
    int n0 = (c0 + TILE_M - 1) / TILE_M;
    int n1 = (c1 + TILE_M - 1) / TILE_M;
    int pair = n0 + n1;
    int xval = pair;
    #pragma unroll
    for (int d = 1; d < 32; d <<= 1) {
        int y = __shfl_up_sync(0xffffffffu, xval, d);
        if (lane >= d) xval += y;
    }
    int t0 = xval - pair;
    int t1 = t0 + n0;
    g_cursor[e0] = t0 * TILE_M;
    g_cursor[e1] = t1 * TILE_M;
    for (int i = 0; i < n0; i++) g_tile_expert[t0 + i] = e0;
    for (int i = 0; i < n1; i++) g_tile_expert[t1 + i] = e1;
}

// ---------------- fill ----------------
__global__ void k_fill() {
    int idx = blockIdx.x * blockDim.x + threadIdx.x;
    if (idx < TK) {
        int e = g_topk_e[idx];
        int p = atomicAdd(&g_cursor[e], 1);
        g_token_list[p] = idx >> 3;
        g_pair_slot[idx] = p;
    }
}

typedef wmma::fragment<wmma::matrix_a, 16, 16, 16, __half, wmma::row_major> FragA;
typedef wmma::fragment<wmma::matrix_b, 16, 16, 16, __half, wmma::col_major> FragB;
typedef wmma::fragment<wmma::accumulator, 16, 16, 16, float> FragC;

// ---------------- fused gate+up GEMM: 128 thr, tile 128 x 64(g)+64(u) ------
// grid (MAX_TILES, IDIM/64)
__global__ __launch_bounds__(128, 2) void k_gemm_gu(
    const __half* __restrict__ Xh,
    const __half* __restrict__ Gp, const __half* __restrict__ Up)
{
    extern __shared__ __half smh[];
    __shared__ int toks[TILE_M];

    int tileM = blockIdx.x;
    int eid = g_tile_expert[tileM];
    if (eid < 0) return;
    int slot0 = tileM * TILE_M;
    int n0 = blockIdx.y * 64;
    const __half* Gexp = Gp + (size_t)eid * IDIM * HID;
    const __half* Uexp = Up + (size_t)eid * IDIM * HID;

    int tid = threadIdx.x;            // 0..127
    toks[tid] = g_token_list[slot0 + tid];
    __syncthreads();

    uint32_t s_base = (uint32_t)__cvta_generic_to_shared(smh);

    // stage: A 128x64h; B rows 0-63 = gate[n0..n0+63], rows 64-127 = up[...]
    auto issue = [&](int s, int k0) {
        uint32_t ab = s_base + (uint32_t)(s * ST_HL) * 2;
        uint32_t bb = ab + (uint32_t)A_HL * 2;
        #pragma unroll
        for (int p = 0; p < 8; p++) {
            int lin = p * 128 + tid;
            int r = lin >> 3, c = lin & 7;
            uint32_t doff = (uint32_t)(r * HS_STRIDE + c * 8) * 2;
            int tk = toks[r];
            const __half* src = Xh + (size_t)(tk < 0 ? 0 : tk) * HID + k0 + c * 8;
            cp_async16(ab + doff, src, (tk < 0) ? 0 : 16);
        }
        #pragma unroll
        for (int p = 0; p < 8; p++) {
            int lin = p * 128 + tid;
            int r = lin >> 3, c = lin & 7;
            uint32_t doff = (uint32_t)(r * HS_STRIDE + c * 8) * 2;
            const __half* src = (r < 64)
                ? Gexp + (size_t)(n0 + r) * HID + k0 + c * 8
                : Uexp + (size_t)(n0 + r - 64) * HID + k0 + c * 8;
            cp_async16(bb + doff, src, 16);
        }
        cp_commit();
    };

    FragC cg[4][2], cu[4][2];
    #pragma unroll
    for (int i = 0; i < 4; i++)
        #pragma unroll
        for (int j = 0; j < 2; j++) {
            wmma::fill_fragment(cg[i][j], 0.f);
            wmma::fill_fragment(cu[i][j], 0.f);
        }

    int wid = tid >> 5;               // 0..3
    int wm = wid & 1;                 // rows wm*64
    int wn = wid >> 1;                // cols wn*32 (within 64)

    const int KT = HID / BK;          // 32
    issue(0, 0);
    issue(1, BK);

    for (int kt = 0; kt < KT; kt++) {
        cp_wait1();
        __syncthreads();
        if (kt + 2 < KT) issue((kt + 2) % STAGES, (kt + 2) * BK);

        __half* As = smh + (kt % STAGES) * ST_HL;
        __half* Bs = As + A_HL;

        #pragma unroll
        for (int kk = 0; kk < BK; kk += 16) {
            FragA a[4];
            FragB bg[2], bu[2];
            #pragma unroll
            for (int i = 0; i < 4; i++)
                wmma::load_matrix_sync(a[i], As + (wm * 64 + i * 16) * HS_STRIDE + kk, HS_STRIDE);
            #pragma unroll
            for (int j = 0; j < 2; j++) {
                wmma::load_matrix_sync(bg[j], Bs + (wn * 32 + j * 16) * HS_STRIDE + kk, HS_STRIDE);
                wmma::load_matrix_sync(bu[j], Bs + (64 + wn * 32 + j * 16) * HS_STRIDE + kk, HS_STRIDE);
            }
            #pragma unroll
            for (int i = 0; i < 4; i++)
                #pragma unroll
                for (int j = 0; j < 2; j++) {
                    wmma::mma_sync(cg[i][j], a[i], bg[j], cg[i][j]);
                    wmma::mma_sync(cu[i][j], a[i], bu[j], cu[i][j]);
                }
        }
        __syncthreads();
    }

    // register-level SwiGLU: cg and cu share the element<->coordinate map
    #pragma unroll
    for (int i = 0; i < 4; i++)
        #pragma unroll
        for (int j = 0; j < 2; j++)
            #pragma unroll
            for (int t = 0; t < 8; t++) {
                float g = cg[i][j].x[t];
                float u = cu[i][j].x[t];
                cg[i][j].x[t] = (g / (1.f + expf(-g))) * u;
            }

    // stage act (fp32) once, convert to fp16, write
    float* St = (float*)smh;          // 128 x ACT_STRIDE
    #pragma unroll
    for (int i = 0; i < 4; i++)
        #pragma unroll
        for (int j = 0; j < 2; j++)
            wmma::store_matrix_sync(St + (wm * 64 + i * 16) * ACT_STRIDE + wn * 32 + j * 16,
                                    cg[i][j], ACT_STRIDE, wmma::mem_row_major);
    __syncthreads();
    #pragma unroll
    for (int p = 0; p < 16; p++) {
        int lin = p * 128 + tid;      // 2048 groups of 4
        int m = lin >> 4, n4 = lin & 15;
        float4 v = *(float4*)(St + m * ACT_STRIDE + n4 * 4);
        __half2 h0 = __floats2half2_rn(v.x, v.y);
        __half2 h1 = __floats2half2_rn(v.z, v.w);
        uint2 o; o.x = *(unsigned*)&h0; o.y = *(unsigned*)&h1;
        *(uint2*)(g_acth + (size_t)(slot0 + m) * IDIM + n0 + n4 * 4) = o;
    }
}

// ---------------- down GEMM: 128 thr, tile 128x128 --------------------------
// grid (MAX_TILES, HID/128)
__global__ __launch_bounds__(128, 2) void k_gemm_down(const __half* __restrict__ Dp)
{
    extern __shared__ __half smh[];

    int tileM = blockIdx.x;
    int eid = g_tile_expert[tileM];
    if (eid < 0) return;
    int slot0 = tileM * TILE_M;
    int n0 = blockIdx.y * 128;
    const __half* Bexp = Dp + (size_t)eid * HID * IDIM;

    int tid = threadIdx.x;
    uint32_t s_base = (uint32_t)__cvta_generic_to_shared(smh);

    auto issue = [&](int s, int k0) {
        uint32_t ab = s_base + (uint32_t)(s * ST_HL) * 2;
        uint32_t bb = ab + (uint32_t)A_HL * 2;
        #pragma unroll
        for (int p = 0; p < 8; p++) {
            int lin = p * 128 + tid;
            int r = lin >> 3, c = lin & 7;
            uint32_t doff = (uint32_t)(r * HS_STRIDE + c * 8) * 2;
            cp_async16(ab + doff, g_acth + (size_t)(slot0 + r) * IDIM + k0 + c * 8, 16);
        }
        #pragma unroll
        for (int p = 0; p < 8; p++) {
            int lin = p * 128 + tid;
            int r = lin >> 3, c = lin & 7;
            uint32_t doff = (uint32_t)(r * HS_STRIDE + c * 8) * 2;
            cp_async16(bb + doff, Bexp + (size_t)(n0 + r) * IDIM + k0 + c * 8, 16);
        }
        cp_commit();
    };

    FragC c[4][4];
    #pragma unroll
    for (int i = 0; i < 4; i++)
        #pragma unroll
        for (int j = 0; j < 4; j++)
            wmma::fill_fragment(c[i][j], 0.f);

    int wid = tid >> 5;
    int wm = wid & 1;                 // rows wm*64
    int wn = wid >> 1;                // cols wn*64

    const int KT = IDIM / BK;         // 12
    issue(0, 0);
    issue(1, BK);

    for (int kt = 0; kt < KT; kt++) {
        cp_wait1();
        __syncthreads();
        if (kt + 2 < KT) issue((kt + 2) % STAGES, (kt + 2) * BK);

        __half* As = smh + (kt % STAGES) * ST_HL;
        __half* Bs = As + A_HL;

        #pragma unroll
        for (int kk = 0; kk < BK; kk += 16) {
            FragA a[4];
            FragB b[4];
            #pragma unroll
            for (int i = 0; i < 4; i++)
                wmma::load_matrix_sync(a[i], As + (wm * 64 + i * 16) * HS_STRIDE + kk, HS_STRIDE);
            #pragma unroll
            for (int j = 0; j < 4; j++)
                wmma::load_matrix_sync(b[j], Bs + (wn * 64 + j * 16) * HS_STRIDE + kk, HS_STRIDE);
            #pragma unroll
            for (int i = 0; i < 4; i++)
                #pragma unroll
                for (int j = 0; j < 4; j++)
                    wmma::mma_sync(c[i][j], a[i], b[j], c[i][j]);
        }
        __syncthreads();
    }

    float* Cs = (float*)smh;          // 128 x CS_STRIDE (67584 B)
    #pragma unroll
    for (int i = 0; i < 4; i++)
        #pragma unroll
        for (int j = 0; j < 4; j++)
            wmma::store_matrix_sync(Cs + (wm * 64 + i * 16) * CS_STRIDE + wn * 64 + j * 16,
                                    c[i][j], CS_STRIDE, wmma::mem_row_major);
    __syncthreads();
    #pragma unroll
    for (int p = 0; p < 16; p++) {
        int lin = p * 128 + tid;      // 2048 groups of 8
        int m = lin >> 4, n8 = lin & 15;
        float4 v0 = *(float4*)(Cs + m * CS_STRIDE + n8 * 8);
        float4 v1 = *(float4*)(Cs + m * CS_STRIDE + n8 * 8 + 4);
        __half2 h0 = __floats2half2_rn(v0.x, v0.y);
        __half2 h1 = __floats2half2_rn(v0.z, v0.w);
        __half2 h2 = __floats2half2_rn(v1.x, v1.y);
        __half2 h3 = __floats2half2_rn(v1.z, v1.w);
        uint4 o;
        o.x = *(unsigned*)&h0; o.y = *(unsigned*)&h1;
        o.z = *(unsigned*)&h2; o.w = *(unsigned*)&h3;
        *(uint4*)(g_pairouth + (size_t)(slot0 + m) * HID + n0 + n8 * 8) = o;
    }
}

// ---------------- combine ----------------
__global__ __launch_bounds__(256) void k_combine(float* __restrict__ out) {
    size_t idx = (size_t)blockIdx.x * 256 + threadIdx.x;
    int t  = (int)(idx >> 8);
    int h8 = (int)(idx & 255);
    float s[8] = {0.f};
    #pragma unroll
    for (int k = 0; k < TOPK; k++) {
        int pi = t * TOPK + k;
        int p = g_pair_slot[pi];
        float w = g_topk_w[pi];
        uint4 v = *(const uint4*)(g_pairouth + (size_t)p * HID + h8 * 8);
        __half2 h0 = *(__half2*)&v.x, h1 = *(__half2*)&v.y;
        __half2 h2 = *(__half2*)&v.z, h3 = *(__half2*)&v.w;
        float2 f0 = __half22float2(h0), f1 = __half22float2(h1);
        float2 f2 = __half22float2(h2), f3 = __half22float2(h3);
        s[0] += w * f0.x; s[1] += w * f0.y; s[2] += w * f1.x; s[3] += w * f1.y;
        s[4] += w * f2.x; s[5] += w * f2.y; s[6] += w * f3.x; s[7] += w * f3.y;
    }
    float4 o0 = make_float4(s[0], s[1], s[2], s[3]);
    float4 o1 = make_float4(s[4], s[5], s[6], s[7]);
    *(float4*)(out + idx * 8)     = o0;
    *(float4*)(out + idx * 8 + 4) = o1;
}

// ---------------- launch ----------------
extern "C" void kernel_launch(void* const* d_in, const int* in_sizes, int n_in,
                              void* d_out, int out_size) {
    const float* x  = (const float*)d_in[0];
    const float* gw = (const float*)d_in[1];
    const float* gp = (const float*)d_in[2];
    const float* up = (const float*)d_in[3];
    const float* dp = (const float*)d_in[4];
    float* out = (float*)d_out;
    float* out_logits = out + (size_t)T_TOK * HID;
    int write_logits = (out_size >= T_TOK * HID + T_TOK * NEXP) ? 1 : 0;

    static cudaStream_t s_w = nullptr;
    static cudaEvent_t ev_fork = nullptr, ev_b = nullptr, ev_c = nullptr;
    if (!s_w) {
        cudaStreamCreateWithFlags(&s_w, cudaStreamNonBlocking);
        cudaEventCreateWithFlags(&ev_fork, cudaEventDisableTiming);
        cudaEventCreateWithFlags(&ev_b, cudaEventDisableTiming);
        cudaEventCreateWithFlags(&ev_c, cudaEventDisableTiming);
        cudaFuncSetAttribute(k_gemm_gu,
                             cudaFuncAttributeMaxDynamicSharedMemorySize, GEMM_SMEM);
        cudaFuncSetAttribute(k_gemm_down,
                             cudaFuncAttributeMaxDynamicSharedMemorySize, GEMM_SMEM);
    }

    __half *xh_p, *gph_p, *uph_p, *dph_p;
    cudaGetSymbolAddress((void**)&xh_p,  g_xh);
    cudaGetSymbolAddress((void**)&gph_p, g_gph);
    cudaGetSymbolAddress((void**)&uph_p, g_uph);
    cudaGetSymbolAddress((void**)&dph_p, g_dph);

    const size_t W8 = WELEM / 8;
    const size_t X8 = (size_t)T_TOK * HID / 8;

    // fork: weight conversions on side stream
    cudaEventRecord(ev_fork, 0);
    cudaStreamWaitEvent(s_w, ev_fork, 0);
    k_cvt<<<(unsigned)((W8 + 255) / 256), 256, 0, s_w>>>((const float4*)gp, (uint4*)gph_p, W8);
    k_cvt<<<(unsigned)((W8 + 255) / 256), 256, 0, s_w>>>((const float4*)up, (uint4*)uph_p, W8);
    cudaEventRecord(ev_b, s_w);
    k_cvt<<<(unsigned)((W8 + 255) / 256), 256, 0, s_w>>>((const float4*)dp, (uint4*)dph_p, W8);
    cudaEventRecord(ev_c, s_w);

    // main stream: router chain + x conversion
    k_reset<<<(MAXPAD + 255) / 256, 256>>>();
    k_router<<<T_TOK / RTOK, 256>>>(x, gw, out_logits, write_logits);
    k_scan<<<1, 32>>>();
    k_fill<<<(TK + 255) / 256, 256>>>();
    k_cvt<<<(unsigned)((X8 + 255) / 256), 256>>>((const float4*)x, (uint4*)xh_p, X8);

    cudaStreamWaitEvent(0, ev_b, 0);
    k_gemm_gu<<<dim3(MAX_TILES, IDIM / 64), 128, GEMM_SMEM>>>(xh_p, gph_p, uph_p);

    cudaStreamWaitEvent(0, ev_c, 0);
    k_gemm_down<<<dim3(MAX_TILES, HID / 128), 128, GEMM_SMEM>>>(dph_p);

    k_combine<<<T_TOK * HID / 8 / 256, 256>>>(out);
}